// round 16
// baseline (speedup 1.0000x reference)
#include <cuda_runtime.h>
#include <cuda_bf16.h>
#include <cstdint>

// ---------------- problem constants ----------------
#define BNB   16
#define SNS   64
#define CC    480
#define TT    8
#define FYH   28
#define FXW   28
#define OS8   8
#define NDF   256
#define KCENT 64
#define MROWS 1024              // BNB*SNS
#define KDIM  30720             // CC*OS8*OS8
#define HW    784               // FYH*FXW
#define NSPLIT 9                // split-K ways (6x53 + 3x54 slabs of k=64)
#define WT_BLOCKS 7680          // (KDIM/32) * (NDF/32)

// ---------------- device scratch (static, no allocations) ----------------
__device__ float          g_featT[(size_t)BNB * HW * CC];     // [b][y][x][c] fp32
__device__ __nv_bfloat16  g_Ah[(size_t)MROWS * KDIM];         // A hi  [row][p*480+c]
__device__ __nv_bfloat16  g_Al[(size_t)MROWS * KDIM];         // A lo
__device__ __nv_bfloat16  g_Wh[(size_t)NDF * KDIM];           // Wt hi [n][p*480+c]
__device__ __nv_bfloat16  g_Wl[(size_t)NDF * KDIM];           // Wt lo
__device__ float          g_P[(size_t)NSPLIT * MROWS * NDF];  // split-K partials

// ---------------- helpers ----------------
#define SMEM_SWIZZLE_128B(byte_offset) \
    ((byte_offset) ^ (((byte_offset) >> 3) & 0x70))

__device__ __forceinline__ uint32_t smem_to_u32(const void* p) {
    uint32_t a;
    asm("{ .reg .u64 t; cvta.to.shared.u64 t, %1; cvt.u32.u64 %0, t; }" : "=r"(a) : "l"(p));
    return a;
}
__device__ __forceinline__ unsigned short bf16u(float x) {
    __nv_bfloat16 h = __float2bfloat16(x);
    return __bfloat16_as_ushort(h);
}
__device__ __forceinline__ float bf16f(unsigned short u) {
    return __bfloat162float(__ushort_as_bfloat16(u));
}

#define LDSM4(R0, R1, R2, R3, ADDR) \
    asm volatile("ldmatrix.sync.aligned.m8n8.x4.shared.b16 {%0,%1,%2,%3}, [%4];" \
        : "=r"(R0), "=r"(R1), "=r"(R2), "=r"(R3) : "r"(ADDR))

#define MMA16816(C, A, B0, B1) \
    asm volatile("mma.sync.aligned.m16n8k16.row.col.f32.bf16.bf16.f32 " \
        "{%0,%1,%2,%3}, {%4,%5,%6,%7}, {%8,%9}, {%0,%1,%2,%3};" \
        : "+f"((C)[0]), "+f"((C)[1]), "+f"((C)[2]), "+f"((C)[3]) \
        : "r"((A)[0]), "r"((A)[1]), "r"((A)[2]), "r"((A)[3]), "r"(B0), "r"(B1))

#define CPA16(DST, SRC) \
    asm volatile("cp.async.cg.shared.global [%0], [%1], 16;" :: "r"(DST), "l"(SRC))
#define CPA_COMMIT() asm volatile("cp.async.commit_group;" ::: "memory")
#define CPA_WAIT(N)  asm volatile("cp.async.wait_group %0;" :: "n"(N) : "memory")

// ---------------- K0: transpose feat [b][c][y][x] (T=last) -> [b][y][x][c] ----------------
__global__ void k_transpose(const float* __restrict__ zvis) {
    __shared__ float t[32][33];
    int b  = blockIdx.x;
    int c0 = blockIdx.y * 32;
    int h0 = blockIdx.z * 32;
    int tx = threadIdx.x, ty = threadIdx.y;
    const float* src = zvis + (size_t)b * CC * TT * HW + (size_t)(TT - 1) * HW;
#pragma unroll
    for (int j = 0; j < 32; j += 8) {
        int c = c0 + ty + j, h = h0 + tx;
        t[ty + j][tx] = (h < HW) ? src[(size_t)c * (TT * HW) + h] : 0.f;
    }
    __syncthreads();
    float* dst = g_featT + (size_t)b * HW * CC;
#pragma unroll
    for (int j = 0; j < 32; j += 8) {
        int h = h0 + ty + j, c = c0 + tx;
        if (h < HW) dst[(size_t)h * CC + c] = t[tx][ty + j];
    }
}

// ---------------- K1: fused prep — ROI pooling blocks + W transpose blocks ----------------
// R12/R14 version (measured best): direct gathers, L1 captures corner-read reuse.
__global__ void __launch_bounds__(256) k_prep(const float* __restrict__ bboxs,
                                              const float* __restrict__ W) {
    int tid = threadIdx.x;

    if (blockIdx.x < MROWS) {
        // ================= ROI path =================
        int row = blockIdx.x;
        int b   = row >> 6;
        __shared__ int   s_off[64][4];
        __shared__ float s_w[64][4];
        __shared__ int   s_valid[64];
        if (tid < 64) {
            int p = tid;
            float bx1 = bboxs[row * 4 + 0], by1 = bboxs[row * 4 + 1];
            float bx2 = bboxs[row * 4 + 2], by2 = bboxs[row * 4 + 3];
            const float sX = 28.0f / 1920.0f, sY = 28.0f / 1080.0f;
            float x1 = bx1 * sX - 0.5f, y1 = by1 * sY - 0.5f;
            float x2 = bx2 * sX - 0.5f, y2 = by2 * sY - 0.5f;
            float bw = (x2 - x1) / 8.0f, bh = (y2 - y1) / 8.0f;
            int ix = p & 7, iy = p >> 3;
            float X = x1 + ((float)ix + 0.5f) * bw;
            float Y = y1 + ((float)iy + 0.5f) * bh;
            int valid = (Y > -1.0f) && (Y < 28.0f) && (X > -1.0f) && (X < 28.0f);
            float x = fminf(fmaxf(X, 0.f), 27.f);
            float y = fminf(fmaxf(Y, 0.f), 27.f);
            int x0 = (int)floorf(x), y0 = (int)floorf(y);
            int x1i = min(x0 + 1, 27), y1i = min(y0 + 1, 27);
            float lx = x - (float)x0, ly = y - (float)y0;
            s_off[p][0] = (y0 * 28 + x0) * (CC / 4);
            s_off[p][1] = (y0 * 28 + x1i) * (CC / 4);
            s_off[p][2] = (y1i * 28 + x0) * (CC / 4);
            s_off[p][3] = (y1i * 28 + x1i) * (CC / 4);
            s_w[p][0] = (1.f - ly) * (1.f - lx);
            s_w[p][1] = (1.f - ly) * lx;
            s_w[p][2] = ly * (1.f - lx);
            s_w[p][3] = ly * lx;
            s_valid[p] = valid;
        }
        __syncthreads();
        const float4* f = (const float4*)(g_featT + (size_t)b * HW * CC);
        uint2* outh = (uint2*)(g_Ah + (size_t)row * KDIM);
        uint2* outl = (uint2*)(g_Al + (size_t)row * KDIM);
        for (int i = tid; i < 64 * 120; i += 256) {
            int p = i / 120, c4 = i - p * 120;
            float4 r = make_float4(0.f, 0.f, 0.f, 0.f);
            if (s_valid[p]) {
                float4 v00 = f[s_off[p][0] + c4];
                float4 v01 = f[s_off[p][1] + c4];
                float4 v10 = f[s_off[p][2] + c4];
                float4 v11 = f[s_off[p][3] + c4];
                float w0 = s_w[p][0], w1 = s_w[p][1], w2 = s_w[p][2], w3 = s_w[p][3];
                r.x = v00.x * w0 + v01.x * w1 + v10.x * w2 + v11.x * w3;
                r.y = v00.y * w0 + v01.y * w1 + v10.y * w2 + v11.y * w3;
                r.z = v00.z * w0 + v01.z * w1 + v10.z * w2 + v11.z * w3;
                r.w = v00.w * w0 + v01.w * w1 + v10.w * w2 + v11.w * w3;
            }
            unsigned short h0 = bf16u(r.x), h1 = bf16u(r.y), h2 = bf16u(r.z), h3 = bf16u(r.w);
            unsigned short l0 = bf16u(r.x - bf16f(h0));
            unsigned short l1 = bf16u(r.y - bf16f(h1));
            unsigned short l2 = bf16u(r.z - bf16f(h2));
            unsigned short l3 = bf16u(r.w - bf16f(h3));
            outh[p * 120 + c4] = make_uint2((uint32_t)h0 | ((uint32_t)h1 << 16),
                                            (uint32_t)h2 | ((uint32_t)h3 << 16));
            outl[p * 120 + c4] = make_uint2((uint32_t)l0 | ((uint32_t)l1 << 16),
                                            (uint32_t)l2 | ((uint32_t)l3 << 16));
        }
    } else {
        // ================= W transpose path =================
        __shared__ float t[32][33];
        int bid = blockIdx.x - MROWS;            // 0..7679
        int kg0 = (bid % 960) * 32;
        int n0  = (bid / 960) * 32;
        int tx = tid & 31, ty = tid >> 5;        // 32 x 8
#pragma unroll
        for (int j = 0; j < 32; j += 8) {
            int kg = kg0 + ty + j;
            int c = kg % 480, p = kg / 480;
            t[ty + j][tx] = W[(size_t)(c * 64 + p) * NDF + n0 + tx];
        }
        __syncthreads();
#pragma unroll
        for (int j = 0; j < 32; j += 8) {
            int n = n0 + ty + j;
            float v = t[tx][ty + j];
            unsigned short h = bf16u(v);
            unsigned short l = bf16u(v - bf16f(h));
            g_Wh[(size_t)n * KDIM + kg0 + tx] = __ushort_as_bfloat16(h);
            g_Wl[(size_t)n * KDIM + kg0 + tx] = __ushort_as_bfloat16(l);
        }
    }
}

// ---------------- K2: bf16x3 warp-MMA split-K GEMM ----------------
// R15 structure with the stage load split into FOUR 2-cp.async bursts threaded
// through the mma stream (Ah @ top, Al after ldsm kb1, Bh after mma kb0,
// Bl+commit after ldsm kb2). One commit per stage -> wait-group semantics
// unchanged; MMA order unchanged (bit-identical output).
#define G3_STAGE 65536
#define G3_TA_LO 16384u
#define G3_TB_HI 32768u
#define G3_TB_LO 49152u
#define G3_DYN   (3 * G3_STAGE + 1024)

struct Frag {
    uint32_t Ah[2][4], Al[2][4], Bh[4][2], Bl[4][2];
};

__device__ __forceinline__ void ldsm_kb(Frag& F, uint32_t st, int kb,
                                        const uint32_t* baseA, const uint32_t* baseB) {
    const uint32_t ko = (uint32_t)kb * 32u;
#pragma unroll
    for (int mt = 0; mt < 2; mt++) {
        uint32_t sw = SMEM_SWIZZLE_128B(baseA[mt] + ko);
        LDSM4(F.Ah[mt][0], F.Ah[mt][1], F.Ah[mt][2], F.Ah[mt][3], st + sw);
        LDSM4(F.Al[mt][0], F.Al[mt][1], F.Al[mt][2], F.Al[mt][3], st + G3_TA_LO + sw);
    }
#pragma unroll
    for (int g = 0; g < 2; g++) {
        uint32_t sw = SMEM_SWIZZLE_128B(baseB[g] + ko);
        LDSM4(F.Bh[2 * g][0], F.Bh[2 * g][1], F.Bh[2 * g + 1][0], F.Bh[2 * g + 1][1],
              st + G3_TB_HI + sw);
        LDSM4(F.Bl[2 * g][0], F.Bl[2 * g][1], F.Bl[2 * g + 1][0], F.Bl[2 * g + 1][1],
              st + G3_TB_LO + sw);
    }
}

__device__ __forceinline__ void mma_frag(float C[2][4][4], const Frag& F) {
#pragma unroll
    for (int mt = 0; mt < 2; mt++)
#pragma unroll
        for (int nt = 0; nt < 4; nt++)
            MMA16816(C[mt][nt], F.Ah[mt], F.Bh[nt][0], F.Bh[nt][1]);
#pragma unroll
    for (int mt = 0; mt < 2; mt++)
#pragma unroll
        for (int nt = 0; nt < 4; nt++)
            MMA16816(C[mt][nt], F.Ah[mt], F.Bl[nt][0], F.Bl[nt][1]);
#pragma unroll
    for (int mt = 0; mt < 2; mt++)
#pragma unroll
        for (int nt = 0; nt < 4; nt++)
            MMA16816(C[mt][nt], F.Al[mt], F.Bh[nt][0], F.Bh[nt][1]);
}

__global__ void __launch_bounds__(512) k_gemm3() {
    extern __shared__ char smem[];
    uint32_t sbase = (smem_to_u32(smem) + 1023u) & ~1023u;

    const int tid  = threadIdx.x;
    const int lane = tid & 31;
    const int wid  = tid >> 5;          // 0..15
    const int wm   = wid >> 2;          // M warp 0..3 (32 rows)
    const int wn   = wid & 3;           // N warp 0..3 (32 cols)

    const int n0    = blockIdx.x * 128; // 2 N tiles
    const int m0    = blockIdx.y * 128; // 8 M tiles
    const int split = blockIdx.z;       // 9 splits
    const int nsl   = (split < 6) ? 53 : 54;                       // 6*53+3*54 = 480 slabs
    const int kbeg  = ((split < 6) ? split * 53 : 318 + (split - 6) * 54) * 64;

    const int r0 = tid >> 3;            // rows 0..63
    const int c0 = tid & 7;             // 16B chunk in 128B row
    const uint32_t dst0 = SMEM_SWIZZLE_128B((uint32_t)(r0 * 128 + c0 * 16));
    const uint32_t dst1 = SMEM_SWIZZLE_128B((uint32_t)((r0 + 64) * 128 + c0 * 16));
    const __nv_bfloat16* pAh = g_Ah + (size_t)(m0 + r0) * KDIM + c0 * 8;
    const __nv_bfloat16* pAl = g_Al + (size_t)(m0 + r0) * KDIM + c0 * 8;
    const __nv_bfloat16* pBh = g_Wh + (size_t)(n0 + r0) * KDIM + c0 * 8;
    const __nv_bfloat16* pBl = g_Wl + (size_t)(n0 + r0) * KDIM + c0 * 8;
    const size_t rstep = (size_t)64 * KDIM;

    const int o = lane >> 3, li = lane & 7;
    uint32_t baseA[2], baseB[2];
#pragma unroll
    for (int mt = 0; mt < 2; mt++)
        baseA[mt] = (uint32_t)((wm * 32 + mt * 16 + (o & 1) * 8 + li) * 128 + (o >> 1) * 16);
#pragma unroll
    for (int g = 0; g < 2; g++)
        baseB[g]  = (uint32_t)((wn * 32 + g * 16 + (o >> 1) * 8 + li) * 128 + (o & 1) * 16);

    float C[2][4][4];
#pragma unroll
    for (int mt = 0; mt < 2; mt++)
#pragma unroll
        for (int nt = 0; nt < 4; nt++)
#pragma unroll
            for (int q = 0; q < 4; q++) C[mt][nt][q] = 0.f;

    // stage load split into four 2-cp.async bursts; single commit in the last
    auto load_q0 = [&](int s, int buf) {   // Ah
        int kpos = kbeg + s * 64;
        uint32_t st = sbase + (uint32_t)buf * G3_STAGE;
        CPA16(st + dst0, pAh + kpos);
        CPA16(st + dst1, pAh + rstep + kpos);
    };
    auto load_q1 = [&](int s, int buf) {   // Al
        int kpos = kbeg + s * 64;
        uint32_t st = sbase + (uint32_t)buf * G3_STAGE;
        CPA16(st + G3_TA_LO + dst0, pAl + kpos);
        CPA16(st + G3_TA_LO + dst1, pAl + rstep + kpos);
    };
    auto load_q2 = [&](int s, int buf) {   // Bh
        int kpos = kbeg + s * 64;
        uint32_t st = sbase + (uint32_t)buf * G3_STAGE;
        CPA16(st + G3_TB_HI + dst0, pBh + kpos);
        CPA16(st + G3_TB_HI + dst1, pBh + rstep + kpos);
    };
    auto load_q3 = [&](int s, int buf) {   // Bl + commit
        int kpos = kbeg + s * 64;
        uint32_t st = sbase + (uint32_t)buf * G3_STAGE;
        CPA16(st + G3_TB_LO + dst0, pBl + kpos);
        CPA16(st + G3_TB_LO + dst1, pBl + rstep + kpos);
        CPA_COMMIT();
    };

    // prologue: stages 0,1; sync stage 0; preload kb0 of slab 0
    load_q0(0, 0); load_q1(0, 0); load_q2(0, 0); load_q3(0, 0);
    load_q0(1, 1); load_q1(1, 1); load_q2(1, 1); load_q3(1, 1);
    CPA_WAIT(1);
    __syncthreads();

    Frag FA, FB;
    ldsm_kb(FA, sbase, 0, baseA, baseB);

    for (int s = 0; s < nsl; s++) {
        int buf = s - (s / 3) * 3;       // s % 3
        uint32_t st = sbase + (uint32_t)buf * G3_STAGE;
        int b2 = (s + 2) - ((s + 2) / 3) * 3;
        const bool pf = (s + 2 < nsl);

        if (pf) load_q0(s + 2, b2);      // Ah burst (2 ops) at slab top
        ldsm_kb(FB, st, 1, baseA, baseB);
        if (pf) load_q1(s + 2, b2);      // Al burst under mma kb0 launch window
        mma_frag(C, FA);                 // kb0
        if (pf) load_q2(s + 2, b2);      // Bh burst under tensor shadow
        ldsm_kb(FA, st, 2, baseA, baseB);
        if (pf) load_q3(s + 2, b2);      // Bl burst + commit under mma kb1
        mma_frag(C, FB);                 // kb1
        ldsm_kb(FB, st, 3, baseA, baseB);
        mma_frag(C, FA);                 // kb2

        if (s + 1 < nsl) {
            if (pf) { CPA_WAIT(1); } else { CPA_WAIT(0); }
            __syncthreads();
            int bn = (s + 1) - ((s + 1) / 3) * 3;
            uint32_t stn = sbase + (uint32_t)bn * G3_STAGE;
            ldsm_kb(FA, stn, 0, baseA, baseB);
            mma_frag(C, FB);             // kb3 (overlaps next-slab kb0 load)
        } else {
            mma_frag(C, FB);             // final kb3
        }
    }

    float* dst = g_P + (size_t)split * MROWS * NDF;
    const int gq = lane >> 2, tq = lane & 3;
#pragma unroll
    for (int mt = 0; mt < 2; mt++)
#pragma unroll
        for (int nt = 0; nt < 4; nt++) {
            int rr = m0 + wm * 32 + mt * 16 + gq;
            int nn = n0 + wn * 32 + nt * 8 + tq * 2;
            *(float2*)(dst + (size_t)rr * NDF + nn)       = make_float2(C[mt][nt][0], C[mt][nt][1]);
            *(float2*)(dst + (size_t)(rr + 8) * NDF + nn) = make_float2(C[mt][nt][2], C[mt][nt][3]);
        }
}

// ---------------- K3: reduce split-K + bias + spatial, distances (float4), s, argmax ----------------
__global__ void k_final(const float* __restrict__ bboxs,
                        const float* __restrict__ b_vis,
                        const float* __restrict__ W_spc,
                        const float* __restrict__ b_spc,
                        const float* __restrict__ centroids,
                        float* __restrict__ out) {
    int row  = blockIdx.x;
    int tid  = threadIdx.x;
    int lane = tid & 31;
    int w    = tid >> 5;
    __shared__ __align__(16) float zs[NDF];
    __shared__ float sv[KCENT];
    __shared__ float s_sum;
    __shared__ int   s_arg;

    float bx1 = bboxs[row * 4 + 0], by1 = bboxs[row * 4 + 1];
    float bx2 = bboxs[row * 4 + 2], by2 = bboxs[row * 4 + 3];
    float cx = bx1 + (bx2 - bx1) * 0.5f;
    float cy = by1 + (by2 - by1) * 0.5f;
    float dx = cx - 960.0f, dy = cy - 540.0f;
    float nrm = sqrtf(dx * dx + dy * dy) / sqrtf(960.0f * 960.0f + 540.0f * 540.0f);

    const float* P = g_P + (size_t)row * NDF + tid;
    float acc = 0.f;
#pragma unroll
    for (int s = 0; s < NSPLIT; s++)
        acc += P[(size_t)s * MROWS * NDF];
    float z = acc + b_vis[tid] + nrm * W_spc[tid] + b_spc[tid];
    out[(size_t)row * NDF + tid] = z;
    zs[tid] = z;
    __syncthreads();

    const float4* zs4 = (const float4*)zs;
#pragma unroll
    for (int kk = 0; kk < 8; kk++) {
        int k = w * 8 + kk;
        const float4* cen4 = (const float4*)(centroids + (size_t)k * NDF);
        float d2 = 0.f;
#pragma unroll
        for (int j = 0; j < 2; j++) {
            int idx = j * 32 + lane;
            float4 a = zs4[idx];
            float4 c = cen4[idx];
            float t0 = a.x - c.x, t1 = a.y - c.y, t2 = a.z - c.z, t3 = a.w - c.w;
            d2 = fmaf(t0, t0, d2);
            d2 = fmaf(t1, t1, d2);
            d2 = fmaf(t2, t2, d2);
            d2 = fmaf(t3, t3, d2);
        }
#pragma unroll
        for (int oo = 16; oo > 0; oo >>= 1) d2 += __shfl_xor_sync(0xffffffffu, d2, oo);
        if (lane == 0) sv[k] = 1.0f / (1.0f + sqrtf(d2));
    }
    __syncthreads();

    if (tid < 32) {
        float a = sv[tid], b = sv[tid + 32];
        float vsum = a + b;
        float m  = (a >= b) ? a : b;
        int   mi = (a >= b) ? tid : tid + 32;
#pragma unroll
        for (int oo = 16; oo > 0; oo >>= 1) {
            vsum += __shfl_xor_sync(0xffffffffu, vsum, oo);
            float om = __shfl_xor_sync(0xffffffffu, m, oo);
            int   oi = __shfl_xor_sync(0xffffffffu, mi, oo);
            if (om > m || (om == m && oi < mi)) { m = om; mi = oi; }
        }
        if (tid == 0) { s_sum = vsum; s_arg = mi; }
    }
    __syncthreads();

    if (tid < KCENT)
        out[(size_t)MROWS * NDF + (size_t)row * KCENT + tid] = sv[tid] / s_sum;
    if (tid == 0)
        out[(size_t)MROWS * NDF + (size_t)MROWS * KCENT + row] = (float)s_arg;
}

// ---------------- launch ----------------
extern "C" void kernel_launch(void* const* d_in, const int* in_sizes, int n_in,
                              void* d_out, int out_size) {
    const float* z_vis = (const float*)d_in[0];
    const float* bboxs = (const float*)d_in[1];
    const float* W_vis = (const float*)d_in[2];
    const float* b_vis = (const float*)d_in[3];
    const float* W_spc = (const float*)d_in[4];
    const float* b_spc = (const float*)d_in[5];
    const float* cent  = (const float*)d_in[6];
    float* out = (float*)d_out;
    (void)in_sizes; (void)n_in; (void)out_size;

    cudaFuncSetAttribute(k_gemm3, cudaFuncAttributeMaxDynamicSharedMemorySize, G3_DYN);

    k_transpose<<<dim3(16, 15, 25), dim3(32, 8)>>>(z_vis);
    k_prep<<<MROWS + WT_BLOCKS, 256>>>(bboxs, W_vis);
    k_gemm3<<<dim3(2, 8, NSPLIT), 512, G3_DYN>>>();
    k_final<<<MROWS, 256>>>(bboxs, b_vis, W_spc, b_spc, cent, out);
}

// round 17
// speedup vs baseline: 1.0130x; 1.0130x over previous
#include <cuda_runtime.h>
#include <cuda_bf16.h>
#include <cstdint>

// ---------------- problem constants ----------------
#define BNB   16
#define SNS   64
#define CC    480
#define TT    8
#define FYH   28
#define FXW   28
#define OS8   8
#define NDF   256
#define KCENT 64
#define MROWS 1024              // BNB*SNS
#define KDIM  30720             // CC*OS8*OS8
#define HW    784               // FYH*FXW
#define NSPLIT 9                // split-K ways (6x53 + 3x54 slabs of k=64)
#define WT_BLOCKS 7680          // (KDIM/32) * (NDF/32)

// ---------------- device scratch (static, no allocations) ----------------
__device__ float          g_featT[(size_t)BNB * HW * CC];     // [b][y][x][c] fp32
__device__ __nv_bfloat16  g_Ah[(size_t)MROWS * KDIM];         // A hi  [row][p*480+c]
__device__ __nv_bfloat16  g_Al[(size_t)MROWS * KDIM];         // A lo
__device__ __nv_bfloat16  g_Wh[(size_t)NDF * KDIM];           // Wt hi [n][p*480+c]
__device__ __nv_bfloat16  g_Wl[(size_t)NDF * KDIM];           // Wt lo
__device__ float          g_P[(size_t)NSPLIT * MROWS * NDF];  // split-K partials

// ---------------- helpers ----------------
#define SMEM_SWIZZLE_128B(byte_offset) \
    ((byte_offset) ^ (((byte_offset) >> 3) & 0x70))

__device__ __forceinline__ uint32_t smem_to_u32(const void* p) {
    uint32_t a;
    asm("{ .reg .u64 t; cvta.to.shared.u64 t, %1; cvt.u32.u64 %0, t; }" : "=r"(a) : "l"(p));
    return a;
}
__device__ __forceinline__ unsigned short bf16u(float x) {
    __nv_bfloat16 h = __float2bfloat16(x);
    return __bfloat16_as_ushort(h);
}
__device__ __forceinline__ float bf16f(unsigned short u) {
    return __bfloat162float(__ushort_as_bfloat16(u));
}

#define LDSM4(R0, R1, R2, R3, ADDR) \
    asm volatile("ldmatrix.sync.aligned.m8n8.x4.shared.b16 {%0,%1,%2,%3}, [%4];" \
        : "=r"(R0), "=r"(R1), "=r"(R2), "=r"(R3) : "r"(ADDR))

#define MMA16816(C, A, B0, B1) \
    asm volatile("mma.sync.aligned.m16n8k16.row.col.f32.bf16.bf16.f32 " \
        "{%0,%1,%2,%3}, {%4,%5,%6,%7}, {%8,%9}, {%0,%1,%2,%3};" \
        : "+f"((C)[0]), "+f"((C)[1]), "+f"((C)[2]), "+f"((C)[3]) \
        : "r"((A)[0]), "r"((A)[1]), "r"((A)[2]), "r"((A)[3]), "r"(B0), "r"(B1))

#define CPA16(DST, SRC) \
    asm volatile("cp.async.cg.shared.global [%0], [%1], 16;" :: "r"(DST), "l"(SRC))
#define CPA_COMMIT() asm volatile("cp.async.commit_group;" ::: "memory")
#define CPA_WAIT(N)  asm volatile("cp.async.wait_group %0;" :: "n"(N) : "memory")

// ---------------- K0: transpose feat [b][c][y][x] (T=last) -> [b][y][x][c] ----------------
__global__ void k_transpose(const float* __restrict__ zvis) {
    __shared__ float t[32][33];
    int b  = blockIdx.x;
    int c0 = blockIdx.y * 32;
    int h0 = blockIdx.z * 32;
    int tx = threadIdx.x, ty = threadIdx.y;
    const float* src = zvis + (size_t)b * CC * TT * HW + (size_t)(TT - 1) * HW;
#pragma unroll
    for (int j = 0; j < 32; j += 8) {
        int c = c0 + ty + j, h = h0 + tx;
        t[ty + j][tx] = (h < HW) ? src[(size_t)c * (TT * HW) + h] : 0.f;
    }
    __syncthreads();
    float* dst = g_featT + (size_t)b * HW * CC;
#pragma unroll
    for (int j = 0; j < 32; j += 8) {
        int h = h0 + ty + j, c = c0 + tx;
        if (h < HW) dst[(size_t)h * CC + c] = t[tx][ty + j];
    }
}

// ---------------- K1: fused prep — ROI pooling blocks + W transpose blocks ----------------
// R12/R14 version (measured best): direct gathers, L1 captures corner-read reuse.
__global__ void __launch_bounds__(256) k_prep(const float* __restrict__ bboxs,
                                              const float* __restrict__ W) {
    int tid = threadIdx.x;

    if (blockIdx.x < MROWS) {
        // ================= ROI path =================
        int row = blockIdx.x;
        int b   = row >> 6;
        __shared__ int   s_off[64][4];
        __shared__ float s_w[64][4];
        __shared__ int   s_valid[64];
        if (tid < 64) {
            int p = tid;
            float bx1 = bboxs[row * 4 + 0], by1 = bboxs[row * 4 + 1];
            float bx2 = bboxs[row * 4 + 2], by2 = bboxs[row * 4 + 3];
            const float sX = 28.0f / 1920.0f, sY = 28.0f / 1080.0f;
            float x1 = bx1 * sX - 0.5f, y1 = by1 * sY - 0.5f;
            float x2 = bx2 * sX - 0.5f, y2 = by2 * sY - 0.5f;
            float bw = (x2 - x1) / 8.0f, bh = (y2 - y1) / 8.0f;
            int ix = p & 7, iy = p >> 3;
            float X = x1 + ((float)ix + 0.5f) * bw;
            float Y = y1 + ((float)iy + 0.5f) * bh;
            int valid = (Y > -1.0f) && (Y < 28.0f) && (X > -1.0f) && (X < 28.0f);
            float x = fminf(fmaxf(X, 0.f), 27.f);
            float y = fminf(fmaxf(Y, 0.f), 27.f);
            int x0 = (int)floorf(x), y0 = (int)floorf(y);
            int x1i = min(x0 + 1, 27), y1i = min(y0 + 1, 27);
            float lx = x - (float)x0, ly = y - (float)y0;
            s_off[p][0] = (y0 * 28 + x0) * (CC / 4);
            s_off[p][1] = (y0 * 28 + x1i) * (CC / 4);
            s_off[p][2] = (y1i * 28 + x0) * (CC / 4);
            s_off[p][3] = (y1i * 28 + x1i) * (CC / 4);
            s_w[p][0] = (1.f - ly) * (1.f - lx);
            s_w[p][1] = (1.f - ly) * lx;
            s_w[p][2] = ly * (1.f - lx);
            s_w[p][3] = ly * lx;
            s_valid[p] = valid;
        }
        __syncthreads();
        const float4* f = (const float4*)(g_featT + (size_t)b * HW * CC);
        uint2* outh = (uint2*)(g_Ah + (size_t)row * KDIM);
        uint2* outl = (uint2*)(g_Al + (size_t)row * KDIM);
        for (int i = tid; i < 64 * 120; i += 256) {
            int p = i / 120, c4 = i - p * 120;
            float4 r = make_float4(0.f, 0.f, 0.f, 0.f);
            if (s_valid[p]) {
                float4 v00 = f[s_off[p][0] + c4];
                float4 v01 = f[s_off[p][1] + c4];
                float4 v10 = f[s_off[p][2] + c4];
                float4 v11 = f[s_off[p][3] + c4];
                float w0 = s_w[p][0], w1 = s_w[p][1], w2 = s_w[p][2], w3 = s_w[p][3];
                r.x = v00.x * w0 + v01.x * w1 + v10.x * w2 + v11.x * w3;
                r.y = v00.y * w0 + v01.y * w1 + v10.y * w2 + v11.y * w3;
                r.z = v00.z * w0 + v01.z * w1 + v10.z * w2 + v11.z * w3;
                r.w = v00.w * w0 + v01.w * w1 + v10.w * w2 + v11.w * w3;
            }
            unsigned short h0 = bf16u(r.x), h1 = bf16u(r.y), h2 = bf16u(r.z), h3 = bf16u(r.w);
            unsigned short l0 = bf16u(r.x - bf16f(h0));
            unsigned short l1 = bf16u(r.y - bf16f(h1));
            unsigned short l2 = bf16u(r.z - bf16f(h2));
            unsigned short l3 = bf16u(r.w - bf16f(h3));
            outh[p * 120 + c4] = make_uint2((uint32_t)h0 | ((uint32_t)h1 << 16),
                                            (uint32_t)h2 | ((uint32_t)h3 << 16));
            outl[p * 120 + c4] = make_uint2((uint32_t)l0 | ((uint32_t)l1 << 16),
                                            (uint32_t)l2 | ((uint32_t)l3 << 16));
        }
    } else {
        // ================= W transpose path =================
        __shared__ float t[32][33];
        int bid = blockIdx.x - MROWS;            // 0..7679
        int kg0 = (bid % 960) * 32;
        int n0  = (bid / 960) * 32;
        int tx = tid & 31, ty = tid >> 5;        // 32 x 8
#pragma unroll
        for (int j = 0; j < 32; j += 8) {
            int kg = kg0 + ty + j;
            int c = kg % 480, p = kg / 480;
            t[ty + j][tx] = W[(size_t)(c * 64 + p) * NDF + n0 + tx];
        }
        __syncthreads();
#pragma unroll
        for (int j = 0; j < 32; j += 8) {
            int n = n0 + ty + j;
            float v = t[tx][ty + j];
            unsigned short h = bf16u(v);
            unsigned short l = bf16u(v - bf16f(h));
            g_Wh[(size_t)n * KDIM + kg0 + tx] = __ushort_as_bfloat16(h);
            g_Wl[(size_t)n * KDIM + kg0 + tx] = __ushort_as_bfloat16(l);
        }
    }
}

// ---------------- K2: bf16x3 warp-MMA split-K GEMM ----------------
// R15 configuration (measured best GEMM: ~97.5us). Per-slab stage load split
// in TWO halves: A-tiles at slab top, B-tiles (+ the single commit) after the
// first mma_frag, moving ~half the LSU burst out of the LDSM-critical slab
// head. One commit per stage -> wait-group semantics unchanged.
#define G3_STAGE 65536
#define G3_TA_LO 16384u
#define G3_TB_HI 32768u
#define G3_TB_LO 49152u
#define G3_DYN   (3 * G3_STAGE + 1024)

struct Frag {
    uint32_t Ah[2][4], Al[2][4], Bh[4][2], Bl[4][2];
};

__device__ __forceinline__ void ldsm_kb(Frag& F, uint32_t st, int kb,
                                        const uint32_t* baseA, const uint32_t* baseB) {
    const uint32_t ko = (uint32_t)kb * 32u;
#pragma unroll
    for (int mt = 0; mt < 2; mt++) {
        uint32_t sw = SMEM_SWIZZLE_128B(baseA[mt] + ko);
        LDSM4(F.Ah[mt][0], F.Ah[mt][1], F.Ah[mt][2], F.Ah[mt][3], st + sw);
        LDSM4(F.Al[mt][0], F.Al[mt][1], F.Al[mt][2], F.Al[mt][3], st + G3_TA_LO + sw);
    }
#pragma unroll
    for (int g = 0; g < 2; g++) {
        uint32_t sw = SMEM_SWIZZLE_128B(baseB[g] + ko);
        LDSM4(F.Bh[2 * g][0], F.Bh[2 * g][1], F.Bh[2 * g + 1][0], F.Bh[2 * g + 1][1],
              st + G3_TB_HI + sw);
        LDSM4(F.Bl[2 * g][0], F.Bl[2 * g][1], F.Bl[2 * g + 1][0], F.Bl[2 * g + 1][1],
              st + G3_TB_LO + sw);
    }
}

__device__ __forceinline__ void mma_frag(float C[2][4][4], const Frag& F) {
#pragma unroll
    for (int mt = 0; mt < 2; mt++)
#pragma unroll
        for (int nt = 0; nt < 4; nt++)
            MMA16816(C[mt][nt], F.Ah[mt], F.Bh[nt][0], F.Bh[nt][1]);
#pragma unroll
    for (int mt = 0; mt < 2; mt++)
#pragma unroll
        for (int nt = 0; nt < 4; nt++)
            MMA16816(C[mt][nt], F.Ah[mt], F.Bl[nt][0], F.Bl[nt][1]);
#pragma unroll
    for (int mt = 0; mt < 2; mt++)
#pragma unroll
        for (int nt = 0; nt < 4; nt++)
            MMA16816(C[mt][nt], F.Al[mt], F.Bh[nt][0], F.Bh[nt][1]);
}

__global__ void __launch_bounds__(512) k_gemm3() {
    extern __shared__ char smem[];
    uint32_t sbase = (smem_to_u32(smem) + 1023u) & ~1023u;

    const int tid  = threadIdx.x;
    const int lane = tid & 31;
    const int wid  = tid >> 5;          // 0..15
    const int wm   = wid >> 2;          // M warp 0..3 (32 rows)
    const int wn   = wid & 3;           // N warp 0..3 (32 cols)

    const int n0    = blockIdx.x * 128; // 2 N tiles
    const int m0    = blockIdx.y * 128; // 8 M tiles
    const int split = blockIdx.z;       // 9 splits
    const int nsl   = (split < 6) ? 53 : 54;                       // 6*53+3*54 = 480 slabs
    const int kbeg  = ((split < 6) ? split * 53 : 318 + (split - 6) * 54) * 64;

    const int r0 = tid >> 3;            // rows 0..63
    const int c0 = tid & 7;             // 16B chunk in 128B row
    const uint32_t dst0 = SMEM_SWIZZLE_128B((uint32_t)(r0 * 128 + c0 * 16));
    const uint32_t dst1 = SMEM_SWIZZLE_128B((uint32_t)((r0 + 64) * 128 + c0 * 16));
    const __nv_bfloat16* pAh = g_Ah + (size_t)(m0 + r0) * KDIM + c0 * 8;
    const __nv_bfloat16* pAl = g_Al + (size_t)(m0 + r0) * KDIM + c0 * 8;
    const __nv_bfloat16* pBh = g_Wh + (size_t)(n0 + r0) * KDIM + c0 * 8;
    const __nv_bfloat16* pBl = g_Wl + (size_t)(n0 + r0) * KDIM + c0 * 8;
    const size_t rstep = (size_t)64 * KDIM;

    const int o = lane >> 3, li = lane & 7;
    uint32_t baseA[2], baseB[2];
#pragma unroll
    for (int mt = 0; mt < 2; mt++)
        baseA[mt] = (uint32_t)((wm * 32 + mt * 16 + (o & 1) * 8 + li) * 128 + (o >> 1) * 16);
#pragma unroll
    for (int g = 0; g < 2; g++)
        baseB[g]  = (uint32_t)((wn * 32 + g * 16 + (o >> 1) * 8 + li) * 128 + (o & 1) * 16);

    float C[2][4][4];
#pragma unroll
    for (int mt = 0; mt < 2; mt++)
#pragma unroll
        for (int nt = 0; nt < 4; nt++)
#pragma unroll
            for (int q = 0; q < 4; q++) C[mt][nt][q] = 0.f;

    // split stage load: A half and B half (single commit in the B half)
    auto load_stage_a = [&](int s, int buf) {
        int kpos = kbeg + s * 64;
        uint32_t st = sbase + (uint32_t)buf * G3_STAGE;
        CPA16(st + dst0,            pAh + kpos);
        CPA16(st + dst1,            pAh + rstep + kpos);
        CPA16(st + G3_TA_LO + dst0, pAl + kpos);
        CPA16(st + G3_TA_LO + dst1, pAl + rstep + kpos);
    };
    auto load_stage_b = [&](int s, int buf) {
        int kpos = kbeg + s * 64;
        uint32_t st = sbase + (uint32_t)buf * G3_STAGE;
        CPA16(st + G3_TB_HI + dst0, pBh + kpos);
        CPA16(st + G3_TB_HI + dst1, pBh + rstep + kpos);
        CPA16(st + G3_TB_LO + dst0, pBl + kpos);
        CPA16(st + G3_TB_LO + dst1, pBl + rstep + kpos);
        CPA_COMMIT();
    };

    // prologue: stages 0,1; sync stage 0; preload kb0 of slab 0
    load_stage_a(0, 0); load_stage_b(0, 0);
    load_stage_a(1, 1); load_stage_b(1, 1);
    CPA_WAIT(1);
    __syncthreads();

    Frag FA, FB;
    ldsm_kb(FA, sbase, 0, baseA, baseB);

    for (int s = 0; s < nsl; s++) {
        int buf = s - (s / 3) * 3;       // s % 3
        uint32_t st = sbase + (uint32_t)buf * G3_STAGE;
        int b2 = (s + 2) - ((s + 2) / 3) * 3;

        // stage s+2, A half at slab top
        if (s + 2 < nsl) load_stage_a(s + 2, b2);

        ldsm_kb(FB, st, 1, baseA, baseB);
        mma_frag(C, FA);                 // kb0

        // stage s+2, B half under tensor shadow (carries the commit)
        if (s + 2 < nsl) load_stage_b(s + 2, b2);

        ldsm_kb(FA, st, 2, baseA, baseB);
        mma_frag(C, FB);                 // kb1
        ldsm_kb(FB, st, 3, baseA, baseB);
        mma_frag(C, FA);                 // kb2

        if (s + 1 < nsl) {
            if (s + 2 < nsl) { CPA_WAIT(1); } else { CPA_WAIT(0); }
            __syncthreads();
            int bn = (s + 1) - ((s + 1) / 3) * 3;
            uint32_t stn = sbase + (uint32_t)bn * G3_STAGE;
            ldsm_kb(FA, stn, 0, baseA, baseB);
            mma_frag(C, FB);             // kb3 (overlaps next-slab kb0 load)
        } else {
            mma_frag(C, FB);             // final kb3
        }
    }

    float* dst = g_P + (size_t)split * MROWS * NDF;
    const int gq = lane >> 2, tq = lane & 3;
#pragma unroll
    for (int mt = 0; mt < 2; mt++)
#pragma unroll
        for (int nt = 0; nt < 4; nt++) {
            int rr = m0 + wm * 32 + mt * 16 + gq;
            int nn = n0 + wn * 32 + nt * 8 + tq * 2;
            *(float2*)(dst + (size_t)rr * NDF + nn)       = make_float2(C[mt][nt][0], C[mt][nt][1]);
            *(float2*)(dst + (size_t)(rr + 8) * NDF + nn) = make_float2(C[mt][nt][2], C[mt][nt][3]);
        }
}

// ---------------- K3: reduce split-K + bias + spatial, distances (float4), s, argmax ----------------
__global__ void k_final(const float* __restrict__ bboxs,
                        const float* __restrict__ b_vis,
                        const float* __restrict__ W_spc,
                        const float* __restrict__ b_spc,
                        const float* __restrict__ centroids,
                        float* __restrict__ out) {
    int row  = blockIdx.x;
    int tid  = threadIdx.x;
    int lane = tid & 31;
    int w    = tid >> 5;
    __shared__ __align__(16) float zs[NDF];
    __shared__ float sv[KCENT];
    __shared__ float s_sum;
    __shared__ int   s_arg;

    float bx1 = bboxs[row * 4 + 0], by1 = bboxs[row * 4 + 1];
    float bx2 = bboxs[row * 4 + 2], by2 = bboxs[row * 4 + 3];
    float cx = bx1 + (bx2 - bx1) * 0.5f;
    float cy = by1 + (by2 - by1) * 0.5f;
    float dx = cx - 960.0f, dy = cy - 540.0f;
    float nrm = sqrtf(dx * dx + dy * dy) / sqrtf(960.0f * 960.0f + 540.0f * 540.0f);

    const float* P = g_P + (size_t)row * NDF + tid;
    float acc = 0.f;
#pragma unroll
    for (int s = 0; s < NSPLIT; s++)
        acc += P[(size_t)s * MROWS * NDF];
    float z = acc + b_vis[tid] + nrm * W_spc[tid] + b_spc[tid];
    out[(size_t)row * NDF + tid] = z;
    zs[tid] = z;
    __syncthreads();

    const float4* zs4 = (const float4*)zs;
#pragma unroll
    for (int kk = 0; kk < 8; kk++) {
        int k = w * 8 + kk;
        const float4* cen4 = (const float4*)(centroids + (size_t)k * NDF);
        float d2 = 0.f;
#pragma unroll
        for (int j = 0; j < 2; j++) {
            int idx = j * 32 + lane;
            float4 a = zs4[idx];
            float4 c = cen4[idx];
            float t0 = a.x - c.x, t1 = a.y - c.y, t2 = a.z - c.z, t3 = a.w - c.w;
            d2 = fmaf(t0, t0, d2);
            d2 = fmaf(t1, t1, d2);
            d2 = fmaf(t2, t2, d2);
            d2 = fmaf(t3, t3, d2);
        }
#pragma unroll
        for (int oo = 16; oo > 0; oo >>= 1) d2 += __shfl_xor_sync(0xffffffffu, d2, oo);
        if (lane == 0) sv[k] = 1.0f / (1.0f + sqrtf(d2));
    }
    __syncthreads();

    if (tid < 32) {
        float a = sv[tid], b = sv[tid + 32];
        float vsum = a + b;
        float m  = (a >= b) ? a : b;
        int   mi = (a >= b) ? tid : tid + 32;
#pragma unroll
        for (int oo = 16; oo > 0; oo >>= 1) {
            vsum += __shfl_xor_sync(0xffffffffu, vsum, oo);
            float om = __shfl_xor_sync(0xffffffffu, m, oo);
            int   oi = __shfl_xor_sync(0xffffffffu, mi, oo);
            if (om > m || (om == m && oi < mi)) { m = om; mi = oi; }
        }
        if (tid == 0) { s_sum = vsum; s_arg = mi; }
    }
    __syncthreads();

    if (tid < KCENT)
        out[(size_t)MROWS * NDF + (size_t)row * KCENT + tid] = sv[tid] / s_sum;
    if (tid == 0)
        out[(size_t)MROWS * NDF + (size_t)MROWS * KCENT + row] = (float)s_arg;
}

// ---------------- launch ----------------
extern "C" void kernel_launch(void* const* d_in, const int* in_sizes, int n_in,
                              void* d_out, int out_size) {
    const float* z_vis = (const float*)d_in[0];
    const float* bboxs = (const float*)d_in[1];
    const float* W_vis = (const float*)d_in[2];
    const float* b_vis = (const float*)d_in[3];
    const float* W_spc = (const float*)d_in[4];
    const float* b_spc = (const float*)d_in[5];
    const float* cent  = (const float*)d_in[6];
    float* out = (float*)d_out;
    (void)in_sizes; (void)n_in; (void)out_size;

    cudaFuncSetAttribute(k_gemm3, cudaFuncAttributeMaxDynamicSharedMemorySize, G3_DYN);

    k_transpose<<<dim3(16, 15, 25), dim3(32, 8)>>>(z_vis);
    k_prep<<<MROWS + WT_BLOCKS, 256>>>(bboxs, W_vis);
    k_gemm3<<<dim3(2, 8, NSPLIT), 512, G3_DYN>>>();
    k_final<<<MROWS, 256>>>(bboxs, b_vis, W_spc, b_spc, cent, out);
}